// round 1
// baseline (speedup 1.0000x reference)
#include <cuda_runtime.h>
#include <cuda_bf16.h>
#include <math.h>

// Problem dims
#define Bsz 256
#define Tlen 64
#define EMB 256
#define UNITS 512
#define G4 2048          // 4*UNITS
#define N2 4096          // fwd+bwd gate width
#define ROWS (Bsz*Tlen)  // 16384

// ---------------- scratch (device globals; no allocation allowed) ----------
__device__ float g_pooled[Bsz * 2048];
__device__ float g_xw[(size_t)ROWS * N2];      // 256 MiB, reused L1 then L2
__device__ float g_seq1[(size_t)ROWS * 1024];  // lstm1 output sequence
__device__ float g_z[Bsz * N2];                // per-step gate pre-activations
__device__ float g_h[2 * Bsz * UNITS];         // [dir][b][u]
__device__ float g_c[2 * Bsz * UNITS];
__device__ float g_feats[Bsz * 3072];
__device__ float g_x1[Bsz * 1024];
__device__ float g_x2[Bsz * 512];

#define TILE 64
#define BK 16

// ---------------- pooled mean over 10x10 spatial ---------------------------
__global__ void pool_kernel(const float* __restrict__ enc, float* __restrict__ pooled) {
    int idx = blockIdx.x * blockDim.x + threadIdx.x;  // < 256*2048
    if (idx >= Bsz * 2048) return;
    int b = idx >> 11;
    int c = idx & 2047;
    const float* p = enc + (size_t)b * 100 * 2048 + c;
    float s = 0.f;
#pragma unroll 4
    for (int q = 0; q < 100; q++) s += p[q * 2048];
    pooled[idx] = s * 0.01f;
}

// ---------------- input projection GEMM: C[M,4096] = A[M,K] @ [Wf|Wb] + b --
// gather!=0 : A row m is emb[seq[m]]
__global__ void __launch_bounds__(256)
gemm_proj_kernel(const float* __restrict__ A, const float* __restrict__ emb,
                 const int* __restrict__ seq,
                 const float* __restrict__ Wf, const float* __restrict__ Wb,
                 const float* __restrict__ biasf, const float* __restrict__ biasb,
                 float* __restrict__ C, int M, int K, int gather) {
    __shared__ float As[BK][TILE];
    __shared__ float Bs[BK][TILE];
    int n0 = blockIdx.x * TILE;
    int m0 = blockIdx.y * TILE;
    bool isB = (n0 >= G4);
    const float* W = isB ? Wb : Wf;
    const float* bias = isB ? biasb : biasf;
    int nloc0 = n0 - (isB ? G4 : 0);

    int tid = threadIdx.x;
    int tx = tid & 15, ty = tid >> 4;
    int am = tid >> 2, akq = tid & 3;       // A loader: row m0+am, float4 akq
    int bk = tid >> 4, bnq = tid & 15;      // B loader: k row bk, float4 bnq

    const float* Arow;
    if (gather) Arow = emb + (size_t)seq[m0 + am] * K;
    else        Arow = A + (size_t)(m0 + am) * K;

    float acc[4][4] = {};
    for (int k0 = 0; k0 < K; k0 += BK) {
        float4 av = *(const float4*)(Arow + k0 + akq * 4);
        As[akq * 4 + 0][am] = av.x;
        As[akq * 4 + 1][am] = av.y;
        As[akq * 4 + 2][am] = av.z;
        As[akq * 4 + 3][am] = av.w;
        float4 bv = *(const float4*)(W + (size_t)(k0 + bk) * G4 + nloc0 + bnq * 4);
        *(float4*)&Bs[bk][bnq * 4] = bv;
        __syncthreads();
#pragma unroll
        for (int kk = 0; kk < BK; kk++) {
            float4 a = *(const float4*)&As[kk][ty * 4];
            float4 b = *(const float4*)&Bs[kk][tx * 4];
            acc[0][0] += a.x * b.x; acc[0][1] += a.x * b.y; acc[0][2] += a.x * b.z; acc[0][3] += a.x * b.w;
            acc[1][0] += a.y * b.x; acc[1][1] += a.y * b.y; acc[1][2] += a.y * b.z; acc[1][3] += a.y * b.w;
            acc[2][0] += a.z * b.x; acc[2][1] += a.z * b.y; acc[2][2] += a.z * b.z; acc[2][3] += a.z * b.w;
            acc[3][0] += a.w * b.x; acc[3][1] += a.w * b.y; acc[3][2] += a.w * b.z; acc[3][3] += a.w * b.w;
        }
        __syncthreads();
    }
#pragma unroll
    for (int i = 0; i < 4; i++) {
        int row = m0 + ty * 4 + i;
#pragma unroll
        for (int j = 0; j < 4; j++) {
            int nl = nloc0 + tx * 4 + j;
            C[(size_t)row * N2 + n0 + tx * 4 + j] = acc[i][j] + bias[nl];
        }
    }
}

// ---------------- recurrent GEMM: z[256,4096] = xw_t + h_dir @ Wh_dir ------
__global__ void __launch_bounds__(256)
gemm_rec_kernel(const float* __restrict__ hF, const float* __restrict__ hB,
                const float* __restrict__ WhF, const float* __restrict__ WhB,
                const float* __restrict__ xw, int t_f, int t_b,
                float* __restrict__ z) {
    __shared__ float As[BK][TILE];
    __shared__ float Bs[BK][TILE];
    const int K = UNITS;  // 512
    int n0 = blockIdx.x * TILE;
    int m0 = blockIdx.y * TILE;
    bool isB = (n0 >= G4);
    const float* A = isB ? hB : hF;
    const float* W = isB ? WhB : WhF;
    int t = isB ? t_b : t_f;
    int nloc0 = n0 - (isB ? G4 : 0);

    int tid = threadIdx.x;
    int tx = tid & 15, ty = tid >> 4;
    int am = tid >> 2, akq = tid & 3;
    int bk = tid >> 4, bnq = tid & 15;

    const float* Arow = A + (size_t)(m0 + am) * K;

    float acc[4][4] = {};
    for (int k0 = 0; k0 < K; k0 += BK) {
        float4 av = *(const float4*)(Arow + k0 + akq * 4);
        As[akq * 4 + 0][am] = av.x;
        As[akq * 4 + 1][am] = av.y;
        As[akq * 4 + 2][am] = av.z;
        As[akq * 4 + 3][am] = av.w;
        float4 bv = *(const float4*)(W + (size_t)(k0 + bk) * G4 + nloc0 + bnq * 4);
        *(float4*)&Bs[bk][bnq * 4] = bv;
        __syncthreads();
#pragma unroll
        for (int kk = 0; kk < BK; kk++) {
            float4 a = *(const float4*)&As[kk][ty * 4];
            float4 b = *(const float4*)&Bs[kk][tx * 4];
            acc[0][0] += a.x * b.x; acc[0][1] += a.x * b.y; acc[0][2] += a.x * b.z; acc[0][3] += a.x * b.w;
            acc[1][0] += a.y * b.x; acc[1][1] += a.y * b.y; acc[1][2] += a.y * b.z; acc[1][3] += a.y * b.w;
            acc[2][0] += a.z * b.x; acc[2][1] += a.z * b.y; acc[2][2] += a.z * b.z; acc[2][3] += a.z * b.w;
            acc[3][0] += a.w * b.x; acc[3][1] += a.w * b.y; acc[3][2] += a.w * b.z; acc[3][3] += a.w * b.w;
        }
        __syncthreads();
    }
#pragma unroll
    for (int i = 0; i < 4; i++) {
        int b = m0 + ty * 4 + i;  // batch row
        const float* add = xw + ((size_t)b * Tlen + t) * N2 + n0 + tx * 4;
        float* zr = z + (size_t)b * N2 + n0 + tx * 4;
#pragma unroll
        for (int j = 0; j < 4; j++) zr[j] = acc[i][j] + add[j];
    }
}

// ---------------- LSTM gate nonlinearity + state update --------------------
__global__ void lstm_gates_kernel(const float* __restrict__ z,
                                  float* __restrict__ h, float* __restrict__ c,
                                  const int* __restrict__ seq, int t_f, int t_b,
                                  float* __restrict__ out_seq) {
    int idx = blockIdx.x * blockDim.x + threadIdx.x;  // < 2*256*512
    if (idx >= 2 * Bsz * UNITS) return;
    int dir = idx >> 17;
    int r = idx & 131071;
    int b = r >> 9;
    int u = r & 511;
    int t = dir ? t_b : t_f;
    const float* zb = z + (size_t)b * N2 + dir * G4;
    float zi = zb[u], zf = zb[512 + u], zg = zb[1024 + u], zo = zb[1536 + u];
    float cv = c[idx], hv = h[idx];
    float si = 1.f / (1.f + expf(-zi));
    float sf = 1.f / (1.f + expf(-zf));
    float so = 1.f / (1.f + expf(-zo));
    float cn = sf * cv + si * tanhf(zg);
    float hn = so * tanhf(cn);
    if (seq[b * Tlen + t] != 0) { cv = cn; hv = hn; }
    c[idx] = cv;
    h[idx] = hv;
    if (out_seq) out_seq[((size_t)b * Tlen + t) * 1024 + dir * 512 + u] = hv;
}

__global__ void zero_kernel(float* p, int n) {
    int i = blockIdx.x * blockDim.x + threadIdx.x;
    if (i < n) p[i] = 0.f;
}

// ---------------- feats = concat(pooled, h_final_f, h_final_b) -------------
__global__ void concat_kernel(const float* __restrict__ pooled,
                              const float* __restrict__ h,
                              float* __restrict__ feats) {
    int idx = blockIdx.x * blockDim.x + threadIdx.x;  // < 256*3072
    if (idx >= Bsz * 3072) return;
    int b = idx / 3072;
    int k = idx - b * 3072;
    float v;
    if (k < 2048) v = pooled[b * 2048 + k];
    else {
        int kk = k - 2048;
        int dir = kk >> 9;
        int u = kk & 511;
        v = h[dir * 131072 + b * 512 + u];
    }
    feats[idx] = v;
}

// ---------------- dense GEMM with relu option ------------------------------
__global__ void __launch_bounds__(256)
gemm_simple_kernel(const float* __restrict__ A, const float* __restrict__ W,
                   const float* __restrict__ bias, float* __restrict__ C,
                   int M, int N, int K, int relu) {
    __shared__ float As[BK][TILE];
    __shared__ float Bs[BK][TILE];
    int n0 = blockIdx.x * TILE;
    int m0 = blockIdx.y * TILE;
    int tid = threadIdx.x;
    int tx = tid & 15, ty = tid >> 4;
    int am = tid >> 2, akq = tid & 3;
    int bk = tid >> 4, bnq = tid & 15;
    const float* Arow = A + (size_t)(m0 + am) * K;

    float acc[4][4] = {};
    for (int k0 = 0; k0 < K; k0 += BK) {
        float4 av = *(const float4*)(Arow + k0 + akq * 4);
        As[akq * 4 + 0][am] = av.x;
        As[akq * 4 + 1][am] = av.y;
        As[akq * 4 + 2][am] = av.z;
        As[akq * 4 + 3][am] = av.w;
        float4 bv = *(const float4*)(W + (size_t)(k0 + bk) * N + n0 + bnq * 4);
        *(float4*)&Bs[bk][bnq * 4] = bv;
        __syncthreads();
#pragma unroll
        for (int kk = 0; kk < BK; kk++) {
            float4 a = *(const float4*)&As[kk][ty * 4];
            float4 b = *(const float4*)&Bs[kk][tx * 4];
            acc[0][0] += a.x * b.x; acc[0][1] += a.x * b.y; acc[0][2] += a.x * b.z; acc[0][3] += a.x * b.w;
            acc[1][0] += a.y * b.x; acc[1][1] += a.y * b.y; acc[1][2] += a.y * b.z; acc[1][3] += a.y * b.w;
            acc[2][0] += a.z * b.x; acc[2][1] += a.z * b.y; acc[2][2] += a.z * b.z; acc[2][3] += a.z * b.w;
            acc[3][0] += a.w * b.x; acc[3][1] += a.w * b.y; acc[3][2] += a.w * b.z; acc[3][3] += a.w * b.w;
        }
        __syncthreads();
    }
#pragma unroll
    for (int i = 0; i < 4; i++) {
        int row = m0 + ty * 4 + i;
#pragma unroll
        for (int j = 0; j < 4; j++) {
            int col = n0 + tx * 4 + j;
            float v = acc[i][j] + bias[col];
            if (relu) v = fmaxf(v, 0.f);
            C[(size_t)row * N + col] = v;
        }
    }
}

// ---------------- final: sigmoid(x2 @ W3 + b3) -----------------------------
__global__ void final_kernel(const float* __restrict__ x2, const float* __restrict__ W3,
                             const float* __restrict__ b3, float* __restrict__ out) {
    int b = blockIdx.x;
    float s = 0.f;
    for (int k = threadIdx.x; k < 512; k += 128) s += x2[b * 512 + k] * W3[k];
    for (int o = 16; o > 0; o >>= 1) s += __shfl_down_sync(0xffffffffu, s, o);
    __shared__ float red[4];
    if ((threadIdx.x & 31) == 0) red[threadIdx.x >> 5] = s;
    __syncthreads();
    if (threadIdx.x == 0) {
        float t = red[0] + red[1] + red[2] + red[3] + b3[0];
        out[b] = 1.f / (1.f + expf(-t));
    }
}

// ---------------------------------------------------------------------------
extern "C" void kernel_launch(void* const* d_in, const int* in_sizes, int n_in,
                              void* d_out, int out_size) {
    const float* enc    = (const float*)d_in[0];
    const int*   seq    = (const int*)d_in[1];
    const float* emb    = (const float*)d_in[2];
    const float* l1f_Wi = (const float*)d_in[3];
    const float* l1f_Wh = (const float*)d_in[4];
    const float* l1f_b  = (const float*)d_in[5];
    const float* l1b_Wi = (const float*)d_in[6];
    const float* l1b_Wh = (const float*)d_in[7];
    const float* l1b_b  = (const float*)d_in[8];
    const float* l2f_Wi = (const float*)d_in[9];
    const float* l2f_Wh = (const float*)d_in[10];
    const float* l2f_b  = (const float*)d_in[11];
    const float* l2b_Wi = (const float*)d_in[12];
    const float* l2b_Wh = (const float*)d_in[13];
    const float* l2b_b  = (const float*)d_in[14];
    const float* W1     = (const float*)d_in[15];
    const float* b1     = (const float*)d_in[16];
    const float* W2     = (const float*)d_in[17];
    const float* b2     = (const float*)d_in[18];
    const float* W3     = (const float*)d_in[19];
    const float* b3     = (const float*)d_in[20];
    float* out = (float*)d_out;

    float *pooled, *xw, *seq1, *zbuf, *h, *c, *feats, *x1, *x2;
    cudaGetSymbolAddress((void**)&pooled, g_pooled);
    cudaGetSymbolAddress((void**)&xw, g_xw);
    cudaGetSymbolAddress((void**)&seq1, g_seq1);
    cudaGetSymbolAddress((void**)&zbuf, g_z);
    cudaGetSymbolAddress((void**)&h, g_h);
    cudaGetSymbolAddress((void**)&c, g_c);
    cudaGetSymbolAddress((void**)&feats, g_feats);
    cudaGetSymbolAddress((void**)&x1, g_x1);
    cudaGetSymbolAddress((void**)&x2, g_x2);

    float* hB = h + 131072;

    // 1. pooled mean
    pool_kernel<<<(Bsz * 2048 + 255) / 256, 256>>>(enc, pooled);

    // 2. layer-1 input projection (embedding gather fused)
    {
        dim3 grid(N2 / TILE, ROWS / TILE);
        gemm_proj_kernel<<<grid, 256>>>(nullptr, emb, seq, l1f_Wi, l1b_Wi,
                                        l1f_b, l1b_b, xw, ROWS, EMB, 1);
    }

    // 3. layer-1 recurrence
    zero_kernel<<<1024, 256>>>(h, 2 * Bsz * UNITS);
    zero_kernel<<<1024, 256>>>(c, 2 * Bsz * UNITS);
    for (int s = 0; s < Tlen; s++) {
        int t_f = s, t_b = Tlen - 1 - s;
        dim3 grid(N2 / TILE, Bsz / TILE);
        gemm_rec_kernel<<<grid, 256>>>(h, hB, l1f_Wh, l1b_Wh, xw, t_f, t_b, zbuf);
        lstm_gates_kernel<<<1024, 256>>>(zbuf, h, c, seq, t_f, t_b, seq1);
    }

    // 4. layer-2 input projection (reuses xw buffer)
    {
        dim3 grid(N2 / TILE, ROWS / TILE);
        gemm_proj_kernel<<<grid, 256>>>(seq1, nullptr, nullptr, l2f_Wi, l2b_Wi,
                                        l2f_b, l2b_b, xw, ROWS, 1024, 0);
    }

    // 5. layer-2 recurrence (no sequence output)
    zero_kernel<<<1024, 256>>>(h, 2 * Bsz * UNITS);
    zero_kernel<<<1024, 256>>>(c, 2 * Bsz * UNITS);
    for (int s = 0; s < Tlen; s++) {
        int t_f = s, t_b = Tlen - 1 - s;
        dim3 grid(N2 / TILE, Bsz / TILE);
        gemm_rec_kernel<<<grid, 256>>>(h, hB, l2f_Wh, l2b_Wh, xw, t_f, t_b, zbuf);
        lstm_gates_kernel<<<1024, 256>>>(zbuf, h, c, seq, t_f, t_b, nullptr);
    }

    // 6. MLP head
    concat_kernel<<<(Bsz * 3072 + 255) / 256, 256>>>(pooled, h, feats);
    {
        dim3 grid(1024 / TILE, Bsz / TILE);
        gemm_simple_kernel<<<grid, 256>>>(feats, W1, b1, x1, Bsz, 1024, 3072, 1);
    }
    {
        dim3 grid(512 / TILE, Bsz / TILE);
        gemm_simple_kernel<<<grid, 256>>>(x1, W2, b2, x2, Bsz, 512, 1024, 1);
    }
    final_kernel<<<Bsz, 128>>>(x2, W3, b3, out);
}

// round 2
// speedup vs baseline: 1.8666x; 1.8666x over previous
#include <cuda_runtime.h>
#include <cuda_bf16.h>
#include <math.h>

// Problem dims
#define Bsz 256
#define Tlen 64
#define EMB 256
#define UNITS 512
#define G4 2048          // 4*UNITS
#define N2 4096          // fwd+bwd gate width
#define ROWS (Bsz*Tlen)  // 16384

// ---------------- scratch (device globals; no allocation allowed) ----------
__device__ float g_pooled[Bsz * 2048];
__device__ float g_xw[(size_t)ROWS * N2];      // 256 MiB, reused L1 then L2
__device__ float g_seq1[(size_t)ROWS * 1024];  // lstm1 output sequence
__device__ float g_z[Bsz * N2];                // per-step gate pre-activations
__device__ float g_h[2 * Bsz * UNITS];         // [dir][b][u]
__device__ float g_c[2 * Bsz * UNITS];
__device__ float g_feats[Bsz * 3072];
__device__ float g_x1[Bsz * 1024];
__device__ float g_x2[Bsz * 512];

// ================= TF32 tensor-core GEMM machinery =========================
#define BM 128
#define BN 64
#define BKK 16
#define ASTRIDE 136   // 128 + 8 pad -> frag LDS conflict-free (mod32 = 8*tg+g)
#define BSTRIDE 72    // 64 + 8 pad

__device__ __forceinline__ unsigned f2tf(float f) {
    unsigned u;
    asm("cvt.rna.tf32.f32 %0, %1;" : "=r"(u) : "f"(f));
    return u;
}

__device__ __forceinline__ void mma_tf32(float* d, const unsigned* a, const unsigned* b) {
    asm volatile(
        "mma.sync.aligned.m16n8k8.row.col.f32.tf32.tf32.f32 "
        "{%0,%1,%2,%3},{%4,%5,%6,%7},{%8,%9},{%0,%1,%2,%3};\n"
        : "+f"(d[0]), "+f"(d[1]), "+f"(d[2]), "+f"(d[3])
        : "r"(a[0]), "r"(a[1]), "r"(a[2]), "r"(a[3]), "r"(b[0]), "r"(b[1]));
}

// Generic C[M,cstride-chunk] = A[M,K] @ W[K,*] (+bias, optional relu).
// gather: if seq != nullptr, A row m = emb[seq[m]].
// split: if 1, block with n0>=2048 uses Wb/biasb (local col n0-2048).
__global__ void __launch_bounds__(256)
tf32_gemm(const float* __restrict__ A, const float* __restrict__ emb,
          const int* __restrict__ seq, int K,
          const float* __restrict__ Wf, const float* __restrict__ Wb, int wstride,
          const float* __restrict__ biasf, const float* __restrict__ biasb,
          float* __restrict__ C, int cstride, int relu, int split) {
    __shared__ unsigned As[BKK * ASTRIDE];
    __shared__ unsigned Bs[BKK * BSTRIDE];

    int n0 = blockIdx.x * BN;
    int m0 = blockIdx.y * BM;
    const float* W = Wf;
    const float* bias = biasf;
    int nloc0 = n0;
    if (split && n0 >= G4) { W = Wb; bias = biasb; nloc0 = n0 - G4; }

    int tid = threadIdx.x;
    int wid = tid >> 5, lane = tid & 31;
    int g = lane >> 2, tg = lane & 3;
    int wm = (wid >> 1) * 32;   // 4 warps along M
    int wn = (wid & 1) * 32;    // 2 warps along N

    // A loader coords: thread handles row r, two float4 at c4
    int ar = tid >> 1;
    int ac = (tid & 1) * 2;
    const float* Arow = seq ? (emb + (size_t)seq[m0 + ar] * K)
                            : (A + (size_t)(m0 + ar) * K);
    // B loader coords
    int bk = tid >> 4, bq = tid & 15;

    float acc[2][4][4] = {};

    for (int k0 = 0; k0 < K; k0 += BKK) {
        // stage A (128x16, transposed to [k][m])
#pragma unroll
        for (int j = 0; j < 2; j++) {
            int c4 = ac + j;
            float4 v = *(const float4*)(Arow + k0 + c4 * 4);
            int kc = c4 * 4;
            As[(kc + 0) * ASTRIDE + ar] = f2tf(v.x);
            As[(kc + 1) * ASTRIDE + ar] = f2tf(v.y);
            As[(kc + 2) * ASTRIDE + ar] = f2tf(v.z);
            As[(kc + 3) * ASTRIDE + ar] = f2tf(v.w);
        }
        // stage B (16x64, [k][n])
        {
            float4 v = *(const float4*)(W + (size_t)(k0 + bk) * wstride + nloc0 + bq * 4);
            uint4 u;
            u.x = f2tf(v.x); u.y = f2tf(v.y); u.z = f2tf(v.z); u.w = f2tf(v.w);
            *(uint4*)&Bs[bk * BSTRIDE + bq * 4] = u;
        }
        __syncthreads();
#pragma unroll
        for (int k8 = 0; k8 < 2; k8++) {
            int kb = k8 * 8;
            unsigned a[2][4], b[4][2];
#pragma unroll
            for (int mi = 0; mi < 2; mi++) {
                int mr = wm + mi * 16;
                a[mi][0] = As[(kb + tg) * ASTRIDE + mr + g];
                a[mi][1] = As[(kb + tg) * ASTRIDE + mr + g + 8];
                a[mi][2] = As[(kb + tg + 4) * ASTRIDE + mr + g];
                a[mi][3] = As[(kb + tg + 4) * ASTRIDE + mr + g + 8];
            }
#pragma unroll
            for (int ni = 0; ni < 4; ni++) {
                int nc = wn + ni * 8;
                b[ni][0] = Bs[(kb + tg) * BSTRIDE + nc + g];
                b[ni][1] = Bs[(kb + tg + 4) * BSTRIDE + nc + g];
            }
#pragma unroll
            for (int mi = 0; mi < 2; mi++)
#pragma unroll
                for (int ni = 0; ni < 4; ni++)
                    mma_tf32(acc[mi][ni], a[mi], b[ni]);
        }
        __syncthreads();
    }

    // epilogue
#pragma unroll
    for (int mi = 0; mi < 2; mi++) {
#pragma unroll
        for (int rh = 0; rh < 2; rh++) {
            int row = m0 + wm + mi * 16 + g + rh * 8;
#pragma unroll
            for (int ni = 0; ni < 4; ni++) {
                int cl = wn + ni * 8 + 2 * tg;  // local col within block
                float v0 = acc[mi][ni][rh * 2 + 0] + bias[nloc0 + cl];
                float v1 = acc[mi][ni][rh * 2 + 1] + bias[nloc0 + cl + 1];
                if (relu) { v0 = fmaxf(v0, 0.f); v1 = fmaxf(v1, 0.f); }
                float2 o = make_float2(v0, v1);
                *(float2*)(C + (size_t)row * cstride + n0 + cl) = o;
            }
        }
    }
}

// Recurrent: z[256,4096] = xw_t + h_dir @ Wh_dir  (bias baked into xw)
__global__ void __launch_bounds__(256)
tf32_rec(const float* __restrict__ hF, const float* __restrict__ hB,
         const float* __restrict__ WhF, const float* __restrict__ WhB,
         const float* __restrict__ xw, int t_f, int t_b,
         float* __restrict__ z) {
    __shared__ unsigned As[BKK * ASTRIDE];
    __shared__ unsigned Bs[BKK * BSTRIDE];
    const int K = UNITS;

    int n0 = blockIdx.x * BN;
    int m0 = blockIdx.y * BM;   // batch rows
    bool isB = (n0 >= G4);
    const float* Ah = isB ? hB : hF;
    const float* W = isB ? WhB : WhF;
    int t = isB ? t_b : t_f;
    int nloc0 = n0 - (isB ? G4 : 0);

    int tid = threadIdx.x;
    int wid = tid >> 5, lane = tid & 31;
    int g = lane >> 2, tg = lane & 3;
    int wm = (wid >> 1) * 32;
    int wn = (wid & 1) * 32;

    int ar = tid >> 1;
    int ac = (tid & 1) * 2;
    const float* Arow = Ah + (size_t)(m0 + ar) * K;
    int bk = tid >> 4, bq = tid & 15;

    float acc[2][4][4] = {};

    for (int k0 = 0; k0 < K; k0 += BKK) {
#pragma unroll
        for (int j = 0; j < 2; j++) {
            int c4 = ac + j;
            float4 v = *(const float4*)(Arow + k0 + c4 * 4);
            int kc = c4 * 4;
            As[(kc + 0) * ASTRIDE + ar] = f2tf(v.x);
            As[(kc + 1) * ASTRIDE + ar] = f2tf(v.y);
            As[(kc + 2) * ASTRIDE + ar] = f2tf(v.z);
            As[(kc + 3) * ASTRIDE + ar] = f2tf(v.w);
        }
        {
            float4 v = *(const float4*)(W + (size_t)(k0 + bk) * G4 + nloc0 + bq * 4);
            uint4 u;
            u.x = f2tf(v.x); u.y = f2tf(v.y); u.z = f2tf(v.z); u.w = f2tf(v.w);
            *(uint4*)&Bs[bk * BSTRIDE + bq * 4] = u;
        }
        __syncthreads();
#pragma unroll
        for (int k8 = 0; k8 < 2; k8++) {
            int kb = k8 * 8;
            unsigned a[2][4], b[4][2];
#pragma unroll
            for (int mi = 0; mi < 2; mi++) {
                int mr = wm + mi * 16;
                a[mi][0] = As[(kb + tg) * ASTRIDE + mr + g];
                a[mi][1] = As[(kb + tg) * ASTRIDE + mr + g + 8];
                a[mi][2] = As[(kb + tg + 4) * ASTRIDE + mr + g];
                a[mi][3] = As[(kb + tg + 4) * ASTRIDE + mr + g + 8];
            }
#pragma unroll
            for (int ni = 0; ni < 4; ni++) {
                int nc = wn + ni * 8;
                b[ni][0] = Bs[(kb + tg) * BSTRIDE + nc + g];
                b[ni][1] = Bs[(kb + tg + 4) * BSTRIDE + nc + g];
            }
#pragma unroll
            for (int mi = 0; mi < 2; mi++)
#pragma unroll
                for (int ni = 0; ni < 4; ni++)
                    mma_tf32(acc[mi][ni], a[mi], b[ni]);
        }
        __syncthreads();
    }

#pragma unroll
    for (int mi = 0; mi < 2; mi++) {
#pragma unroll
        for (int rh = 0; rh < 2; rh++) {
            int b = m0 + wm + mi * 16 + g + rh * 8;  // batch row
            const float* add = xw + ((size_t)b * Tlen + t) * N2 + n0;
            float* zr = z + (size_t)b * N2 + n0;
#pragma unroll
            for (int ni = 0; ni < 4; ni++) {
                int cl = wn + ni * 8 + 2 * tg;
                float2 o;
                o.x = acc[mi][ni][rh * 2 + 0] + add[cl];
                o.y = acc[mi][ni][rh * 2 + 1] + add[cl + 1];
                *(float2*)(zr + cl) = o;
            }
        }
    }
}

// ---------------- pooled mean over 10x10 spatial ---------------------------
__global__ void pool_kernel(const float* __restrict__ enc, float* __restrict__ pooled) {
    int idx = blockIdx.x * blockDim.x + threadIdx.x;
    if (idx >= Bsz * 2048) return;
    int b = idx >> 11;
    int c = idx & 2047;
    const float* p = enc + (size_t)b * 100 * 2048 + c;
    float s = 0.f;
#pragma unroll 4
    for (int q = 0; q < 100; q++) s += p[q * 2048];
    pooled[idx] = s * 0.01f;
}

// ---------------- LSTM gate nonlinearity + state update --------------------
__global__ void lstm_gates_kernel(const float* __restrict__ z,
                                  float* __restrict__ h, float* __restrict__ c,
                                  const int* __restrict__ seq, int t_f, int t_b,
                                  float* __restrict__ out_seq) {
    int idx = blockIdx.x * blockDim.x + threadIdx.x;
    if (idx >= 2 * Bsz * UNITS) return;
    int dir = idx >> 17;
    int r = idx & 131071;
    int b = r >> 9;
    int u = r & 511;
    int t = dir ? t_b : t_f;
    const float* zb = z + (size_t)b * N2 + dir * G4;
    float zi = zb[u], zf = zb[512 + u], zg = zb[1024 + u], zo = zb[1536 + u];
    float cv = c[idx], hv = h[idx];
    float si = 1.f / (1.f + expf(-zi));
    float sf = 1.f / (1.f + expf(-zf));
    float so = 1.f / (1.f + expf(-zo));
    float cn = sf * cv + si * tanhf(zg);
    float hn = so * tanhf(cn);
    if (seq[b * Tlen + t] != 0) { cv = cn; hv = hn; }
    c[idx] = cv;
    h[idx] = hv;
    if (out_seq) out_seq[((size_t)b * Tlen + t) * 1024 + dir * 512 + u] = hv;
}

__global__ void zero_kernel(float* p, int n) {
    int i = blockIdx.x * blockDim.x + threadIdx.x;
    if (i < n) p[i] = 0.f;
}

// ---------------- feats = concat(pooled, h_final_f, h_final_b) -------------
__global__ void concat_kernel(const float* __restrict__ pooled,
                              const float* __restrict__ h,
                              float* __restrict__ feats) {
    int idx = blockIdx.x * blockDim.x + threadIdx.x;
    if (idx >= Bsz * 3072) return;
    int b = idx / 3072;
    int k = idx - b * 3072;
    float v;
    if (k < 2048) v = pooled[b * 2048 + k];
    else {
        int kk = k - 2048;
        int dir = kk >> 9;
        int u = kk & 511;
        v = h[dir * 131072 + b * 512 + u];
    }
    feats[idx] = v;
}

// ---------------- final: sigmoid(x2 @ W3 + b3) -----------------------------
__global__ void final_kernel(const float* __restrict__ x2, const float* __restrict__ W3,
                             const float* __restrict__ b3, float* __restrict__ out) {
    int b = blockIdx.x;
    float s = 0.f;
    for (int k = threadIdx.x; k < 512; k += 128) s += x2[b * 512 + k] * W3[k];
    for (int o = 16; o > 0; o >>= 1) s += __shfl_down_sync(0xffffffffu, s, o);
    __shared__ float red[4];
    if ((threadIdx.x & 31) == 0) red[threadIdx.x >> 5] = s;
    __syncthreads();
    if (threadIdx.x == 0) {
        float t = red[0] + red[1] + red[2] + red[3] + b3[0];
        out[b] = 1.f / (1.f + expf(-t));
    }
}

// ---------------------------------------------------------------------------
extern "C" void kernel_launch(void* const* d_in, const int* in_sizes, int n_in,
                              void* d_out, int out_size) {
    const float* enc    = (const float*)d_in[0];
    const int*   seq    = (const int*)d_in[1];
    const float* emb    = (const float*)d_in[2];
    const float* l1f_Wi = (const float*)d_in[3];
    const float* l1f_Wh = (const float*)d_in[4];
    const float* l1f_b  = (const float*)d_in[5];
    const float* l1b_Wi = (const float*)d_in[6];
    const float* l1b_Wh = (const float*)d_in[7];
    const float* l1b_b  = (const float*)d_in[8];
    const float* l2f_Wi = (const float*)d_in[9];
    const float* l2f_Wh = (const float*)d_in[10];
    const float* l2f_b  = (const float*)d_in[11];
    const float* l2b_Wi = (const float*)d_in[12];
    const float* l2b_Wh = (const float*)d_in[13];
    const float* l2b_b  = (const float*)d_in[14];
    const float* W1     = (const float*)d_in[15];
    const float* b1     = (const float*)d_in[16];
    const float* W2     = (const float*)d_in[17];
    const float* b2     = (const float*)d_in[18];
    const float* W3     = (const float*)d_in[19];
    const float* b3     = (const float*)d_in[20];
    float* out = (float*)d_out;

    float *pooled, *xw, *seq1, *zbuf, *h, *c, *feats, *x1, *x2;
    cudaGetSymbolAddress((void**)&pooled, g_pooled);
    cudaGetSymbolAddress((void**)&xw, g_xw);
    cudaGetSymbolAddress((void**)&seq1, g_seq1);
    cudaGetSymbolAddress((void**)&zbuf, g_z);
    cudaGetSymbolAddress((void**)&h, g_h);
    cudaGetSymbolAddress((void**)&c, g_c);
    cudaGetSymbolAddress((void**)&feats, g_feats);
    cudaGetSymbolAddress((void**)&x1, g_x1);
    cudaGetSymbolAddress((void**)&x2, g_x2);

    float* hB = h + 131072;

    // 1. pooled mean
    pool_kernel<<<(Bsz * 2048 + 255) / 256, 256>>>(enc, pooled);

    // 2. layer-1 input projection (embedding gather fused)
    {
        dim3 grid(N2 / BN, ROWS / BM);
        tf32_gemm<<<grid, 256>>>(nullptr, emb, seq, EMB, l1f_Wi, l1b_Wi, G4,
                                 l1f_b, l1b_b, xw, N2, 0, 1);
    }

    // 3. layer-1 recurrence
    zero_kernel<<<1024, 256>>>(h, 2 * Bsz * UNITS);
    zero_kernel<<<1024, 256>>>(c, 2 * Bsz * UNITS);
    for (int s = 0; s < Tlen; s++) {
        int t_f = s, t_b = Tlen - 1 - s;
        dim3 grid(N2 / BN, Bsz / BM);
        tf32_rec<<<grid, 256>>>(h, hB, l1f_Wh, l1b_Wh, xw, t_f, t_b, zbuf);
        lstm_gates_kernel<<<1024, 256>>>(zbuf, h, c, seq, t_f, t_b, seq1);
    }

    // 4. layer-2 input projection (reuses xw buffer)
    {
        dim3 grid(N2 / BN, ROWS / BM);
        tf32_gemm<<<grid, 256>>>(seq1, nullptr, nullptr, 1024, l2f_Wi, l2b_Wi, G4,
                                 l2f_b, l2b_b, xw, N2, 0, 1);
    }

    // 5. layer-2 recurrence (no sequence output)
    zero_kernel<<<1024, 256>>>(h, 2 * Bsz * UNITS);
    zero_kernel<<<1024, 256>>>(c, 2 * Bsz * UNITS);
    for (int s = 0; s < Tlen; s++) {
        int t_f = s, t_b = Tlen - 1 - s;
        dim3 grid(N2 / BN, Bsz / BM);
        tf32_rec<<<grid, 256>>>(h, hB, l2f_Wh, l2b_Wh, xw, t_f, t_b, zbuf);
        lstm_gates_kernel<<<1024, 256>>>(zbuf, h, c, seq, t_f, t_b, nullptr);
    }

    // 6. MLP head
    concat_kernel<<<(Bsz * 3072 + 255) / 256, 256>>>(pooled, h, feats);
    {
        dim3 grid(1024 / BN, Bsz / BM);
        tf32_gemm<<<grid, 256>>>(feats, nullptr, nullptr, 3072, W1, nullptr, 1024,
                                 b1, nullptr, x1, 1024, 1, 0);
    }
    {
        dim3 grid(512 / BN, Bsz / BM);
        tf32_gemm<<<grid, 256>>>(x1, nullptr, nullptr, 1024, W2, nullptr, 512,
                                 b2, nullptr, x2, 512, 1, 0);
    }
    final_kernel<<<Bsz, 128>>>(x2, W3, b3, out);
}

// round 3
// speedup vs baseline: 1.9587x; 1.0494x over previous
#include <cuda_runtime.h>
#include <cuda_bf16.h>
#include <math.h>

// Problem dims
#define Bsz 256
#define Tlen 64
#define EMB 256
#define UNITS 512
#define G4 2048          // 4*UNITS
#define N2 4096          // fwd+bwd gate width
#define ROWS (Bsz*Tlen)  // 16384

#define NBLK 128         // persistent grid size (single wave on 148 SMs)

// ---------------- scratch (device globals; no allocation allowed) ----------
__device__ float g_pooled[Bsz * 2048];
__device__ float g_xw[(size_t)ROWS * N2];      // 256 MiB, reused L1 then L2
__device__ float g_seq1[(size_t)ROWS * 1024];  // lstm1 output sequence
__device__ float g_z[Bsz * N2];                // per-step gate pre-activations
__device__ float g_h[2 * Bsz * UNITS];         // [dir][b][u]
__device__ float g_c[2 * Bsz * UNITS];
__device__ float g_feats[Bsz * 3072];
__device__ float g_x1[Bsz * 1024];
__device__ float g_x2[Bsz * 512];

// grid barrier state (monotone generation; self-resetting count)
__device__ unsigned g_bar_count;
__device__ volatile unsigned g_bar_gen;

__device__ __forceinline__ void grid_barrier() {
    __syncthreads();
    if (threadIdx.x == 0) {
        unsigned gen = g_bar_gen;
        __threadfence();
        if (atomicAdd(&g_bar_count, 1u) == NBLK - 1) {
            atomicExch(&g_bar_count, 0u);
            __threadfence();
            g_bar_gen = gen + 1;
        } else {
            while (g_bar_gen == gen) __nanosleep(64);
        }
    }
    __syncthreads();
}

// ================= TF32 helpers ============================================
__device__ __forceinline__ unsigned f2tf(float f) {
    unsigned u;
    asm("cvt.rna.tf32.f32 %0, %1;" : "=r"(u) : "f"(f));
    return u;
}

__device__ __forceinline__ void mma_tf32(float* d, const unsigned* a, const unsigned* b) {
    asm volatile(
        "mma.sync.aligned.m16n8k8.row.col.f32.tf32.tf32.f32 "
        "{%0,%1,%2,%3},{%4,%5,%6,%7},{%8,%9},{%0,%1,%2,%3};\n"
        : "+f"(d[0]), "+f"(d[1]), "+f"(d[2]), "+f"(d[3])
        : "r"(a[0]), "r"(a[1]), "r"(a[2]), "r"(a[3]), "r"(b[0]), "r"(b[1]));
}

// ================= persistent BiLSTM recurrence ============================
// Grid: 128 blocks = 2 m-tiles (128 batch) x 64 n-tiles (64 gate cols).
// Each block keeps its Wh[512,64] tile in smem (tf32) for all 64 steps.
#define WH_STRIDE 72                      // 64 + 8 pad: frag reads conflict-free
#define RK 64                             // k-chunk for h staging
#define AS_STRIDE 136                     // 128 + 8 pad
#define REC_SMEM ((512*WH_STRIDE + RK*AS_STRIDE) * 4)

__global__ void __launch_bounds__(256, 1)
rec_persistent(float* __restrict__ h, float* __restrict__ c,
               const float* __restrict__ WhF, const float* __restrict__ WhB,
               const float* __restrict__ xw, const int* __restrict__ seq,
               float* __restrict__ z, float* __restrict__ out_seq) {
    extern __shared__ unsigned smem_dyn[];
    unsigned* Whs = smem_dyn;                 // [512][WH_STRIDE]
    unsigned* As  = smem_dyn + 512 * WH_STRIDE;  // [RK][AS_STRIDE]

    int tid = threadIdx.x;
    int bn = blockIdx.x & 63;
    int bm = blockIdx.x >> 6;
    int n0 = bn * 64;
    int dir = (n0 >= G4) ? 1 : 0;
    int nloc0 = n0 - dir * G4;
    int m0 = bm * 128;
    const float* W = dir ? WhB : WhF;
    const float* hdir = h + dir * (Bsz * UNITS);

    int wid = tid >> 5, lane = tid & 31;
    int g = lane >> 2, tg = lane & 3;
    int wm = (wid >> 1) * 32;   // 4 warps along M (128)
    int wn = (wid & 1) * 32;    // 2 warps along N (64)

    // ---- load Wh tile into smem as tf32 (once per layer) ----
    for (int i = tid; i < 512 * 16; i += 256) {
        int r = i >> 4, q = i & 15;
        float4 v = *(const float4*)(W + (size_t)r * G4 + nloc0 + q * 4);
        unsigned* dst = &Whs[r * WH_STRIDE + q * 4];
        dst[0] = f2tf(v.x); dst[1] = f2tf(v.y); dst[2] = f2tf(v.z); dst[3] = f2tf(v.w);
    }

    // ---- zero this block's h/c slice ----
    {
        int base = blockIdx.x * 2048;
        for (int j = tid; j < 2048; j += 256) { h[base + j] = 0.f; c[base + j] = 0.f; }
    }
    grid_barrier();

    // A staging coords (16-k sub-chunk, R2-proven pattern)
    int ar = tid >> 1;
    int ac = (tid & 1) * 2;
    const float* Arow = hdir + (size_t)(m0 + ar) * UNITS;

    for (int t = 0; t < Tlen; t++) {
        int te = dir ? (Tlen - 1 - t) : t;

        // ================= GEMM phase: z_tile = h @ Wh + xw(te) ============
        float acc[2][4][4] = {};
        for (int k0 = 0; k0 < UNITS; k0 += RK) {
#pragma unroll
            for (int s = 0; s < RK / 16; s++) {
#pragma unroll
                for (int j = 0; j < 2; j++) {
                    int c4 = ac + j;
                    float4 v = *(const float4*)(Arow + k0 + s * 16 + c4 * 4);
                    int kc = s * 16 + c4 * 4;
                    As[(kc + 0) * AS_STRIDE + ar] = f2tf(v.x);
                    As[(kc + 1) * AS_STRIDE + ar] = f2tf(v.y);
                    As[(kc + 2) * AS_STRIDE + ar] = f2tf(v.z);
                    As[(kc + 3) * AS_STRIDE + ar] = f2tf(v.w);
                }
            }
            __syncthreads();
#pragma unroll
            for (int kb = 0; kb < RK; kb += 8) {
                unsigned a[2][4], b[4][2];
#pragma unroll
                for (int mi = 0; mi < 2; mi++) {
                    int mr = wm + mi * 16;
                    a[mi][0] = As[(kb + tg) * AS_STRIDE + mr + g];
                    a[mi][1] = As[(kb + tg) * AS_STRIDE + mr + g + 8];
                    a[mi][2] = As[(kb + tg + 4) * AS_STRIDE + mr + g];
                    a[mi][3] = As[(kb + tg + 4) * AS_STRIDE + mr + g + 8];
                }
                int krow = k0 + kb;
#pragma unroll
                for (int ni = 0; ni < 4; ni++) {
                    int nc = wn + ni * 8;
                    b[ni][0] = Whs[(krow + tg) * WH_STRIDE + nc + g];
                    b[ni][1] = Whs[(krow + tg + 4) * WH_STRIDE + nc + g];
                }
#pragma unroll
                for (int mi = 0; mi < 2; mi++)
#pragma unroll
                    for (int ni = 0; ni < 4; ni++)
                        mma_tf32(acc[mi][ni], a[mi], b[ni]);
            }
            __syncthreads();
        }
        // epilogue: z = acc + xw[b][te][col]
#pragma unroll
        for (int mi = 0; mi < 2; mi++) {
#pragma unroll
            for (int rh = 0; rh < 2; rh++) {
                int b = m0 + wm + mi * 16 + g + rh * 8;
                const float* add = xw + ((size_t)b * Tlen + te) * N2 + n0;
                float* zr = z + (size_t)b * N2 + n0;
#pragma unroll
                for (int ni = 0; ni < 4; ni++) {
                    int cl = wn + ni * 8 + 2 * tg;
                    float2 o;
                    o.x = acc[mi][ni][rh * 2 + 0] + add[cl];
                    o.y = acc[mi][ni][rh * 2 + 1] + add[cl + 1];
                    *(float2*)(zr + cl) = o;
                }
            }
        }
        grid_barrier();

        // ================= gate phase: this block's 2048 state elems =======
        {
            int base = blockIdx.x * 2048;
#pragma unroll
            for (int e = 0; e < 8; e++) {
                int idx = base + tid + e * 256;
                int dir_e = idx >> 17;
                int r = idx & 131071;
                int b = r >> 9;
                int u = r & 511;
                int t_e = dir_e ? (Tlen - 1 - t) : t;
                const float* zb = z + (size_t)b * N2 + dir_e * G4;
                float zi = zb[u], zf = zb[512 + u], zg = zb[1024 + u], zo = zb[1536 + u];
                float cv = c[idx], hv = h[idx];
                float si = 1.f / (1.f + expf(-zi));
                float sf = 1.f / (1.f + expf(-zf));
                float so = 1.f / (1.f + expf(-zo));
                float cn = sf * cv + si * tanhf(zg);
                float hn = so * tanhf(cn);
                if (seq[b * Tlen + t_e] != 0) { cv = cn; hv = hn; }
                c[idx] = cv;
                h[idx] = hv;
                if (out_seq)
                    out_seq[((size_t)b * Tlen + t_e) * 1024 + dir_e * 512 + u] = hv;
            }
        }
        grid_barrier();
    }
}

// ================= TF32 tensor-core GEMM (projections / MLP) ===============
#define BM 128
#define BN 64
#define BKK 16
#define ASTRIDE 136
#define BSTRIDE 72

__global__ void __launch_bounds__(256)
tf32_gemm(const float* __restrict__ A, const float* __restrict__ emb,
          const int* __restrict__ seq, int K,
          const float* __restrict__ Wf, const float* __restrict__ Wb, int wstride,
          const float* __restrict__ biasf, const float* __restrict__ biasb,
          float* __restrict__ C, int cstride, int relu, int split) {
    __shared__ unsigned As[BKK * ASTRIDE];
    __shared__ unsigned Bs[BKK * BSTRIDE];

    int n0 = blockIdx.x * BN;
    int m0 = blockIdx.y * BM;
    const float* W = Wf;
    const float* bias = biasf;
    int nloc0 = n0;
    if (split && n0 >= G4) { W = Wb; bias = biasb; nloc0 = n0 - G4; }

    int tid = threadIdx.x;
    int wid = tid >> 5, lane = tid & 31;
    int g = lane >> 2, tg = lane & 3;
    int wm = (wid >> 1) * 32;
    int wn = (wid & 1) * 32;

    int ar = tid >> 1;
    int ac = (tid & 1) * 2;
    const float* Arow = seq ? (emb + (size_t)seq[m0 + ar] * K)
                            : (A + (size_t)(m0 + ar) * K);
    int bk = tid >> 4, bq = tid & 15;

    float acc[2][4][4] = {};

    for (int k0 = 0; k0 < K; k0 += BKK) {
#pragma unroll
        for (int j = 0; j < 2; j++) {
            int c4 = ac + j;
            float4 v = *(const float4*)(Arow + k0 + c4 * 4);
            int kc = c4 * 4;
            As[(kc + 0) * ASTRIDE + ar] = f2tf(v.x);
            As[(kc + 1) * ASTRIDE + ar] = f2tf(v.y);
            As[(kc + 2) * ASTRIDE + ar] = f2tf(v.z);
            As[(kc + 3) * ASTRIDE + ar] = f2tf(v.w);
        }
        {
            float4 v = *(const float4*)(W + (size_t)(k0 + bk) * wstride + nloc0 + bq * 4);
            uint4 u;
            u.x = f2tf(v.x); u.y = f2tf(v.y); u.z = f2tf(v.z); u.w = f2tf(v.w);
            *(uint4*)&Bs[bk * BSTRIDE + bq * 4] = u;
        }
        __syncthreads();
#pragma unroll
        for (int k8 = 0; k8 < 2; k8++) {
            int kb = k8 * 8;
            unsigned a[2][4], b[4][2];
#pragma unroll
            for (int mi = 0; mi < 2; mi++) {
                int mr = wm + mi * 16;
                a[mi][0] = As[(kb + tg) * ASTRIDE + mr + g];
                a[mi][1] = As[(kb + tg) * ASTRIDE + mr + g + 8];
                a[mi][2] = As[(kb + tg + 4) * ASTRIDE + mr + g];
                a[mi][3] = As[(kb + tg + 4) * ASTRIDE + mr + g + 8];
            }
#pragma unroll
            for (int ni = 0; ni < 4; ni++) {
                int nc = wn + ni * 8;
                b[ni][0] = Bs[(kb + tg) * BSTRIDE + nc + g];
                b[ni][1] = Bs[(kb + tg + 4) * BSTRIDE + nc + g];
            }
#pragma unroll
            for (int mi = 0; mi < 2; mi++)
#pragma unroll
                for (int ni = 0; ni < 4; ni++)
                    mma_tf32(acc[mi][ni], a[mi], b[ni]);
        }
        __syncthreads();
    }

#pragma unroll
    for (int mi = 0; mi < 2; mi++) {
#pragma unroll
        for (int rh = 0; rh < 2; rh++) {
            int row = m0 + wm + mi * 16 + g + rh * 8;
#pragma unroll
            for (int ni = 0; ni < 4; ni++) {
                int cl = wn + ni * 8 + 2 * tg;
                float v0 = acc[mi][ni][rh * 2 + 0] + bias[nloc0 + cl];
                float v1 = acc[mi][ni][rh * 2 + 1] + bias[nloc0 + cl + 1];
                if (relu) { v0 = fmaxf(v0, 0.f); v1 = fmaxf(v1, 0.f); }
                float2 o = make_float2(v0, v1);
                *(float2*)(C + (size_t)row * cstride + n0 + cl) = o;
            }
        }
    }
}

// ---------------- pooled mean over 10x10 spatial ---------------------------
__global__ void pool_kernel(const float* __restrict__ enc, float* __restrict__ pooled) {
    int idx = blockIdx.x * blockDim.x + threadIdx.x;
    if (idx >= Bsz * 2048) return;
    int b = idx >> 11;
    int c = idx & 2047;
    const float* p = enc + (size_t)b * 100 * 2048 + c;
    float s = 0.f;
#pragma unroll 4
    for (int q = 0; q < 100; q++) s += p[q * 2048];
    pooled[idx] = s * 0.01f;
}

// ---------------- feats = concat(pooled, h_final_f, h_final_b) -------------
__global__ void concat_kernel(const float* __restrict__ pooled,
                              const float* __restrict__ h,
                              float* __restrict__ feats) {
    int idx = blockIdx.x * blockDim.x + threadIdx.x;
    if (idx >= Bsz * 3072) return;
    int b = idx / 3072;
    int k = idx - b * 3072;
    float v;
    if (k < 2048) v = pooled[b * 2048 + k];
    else {
        int kk = k - 2048;
        int dir = kk >> 9;
        int u = kk & 511;
        v = h[dir * 131072 + b * 512 + u];
    }
    feats[idx] = v;
}

// ---------------- final: sigmoid(x2 @ W3 + b3) -----------------------------
__global__ void final_kernel(const float* __restrict__ x2, const float* __restrict__ W3,
                             const float* __restrict__ b3, float* __restrict__ out) {
    int b = blockIdx.x;
    float s = 0.f;
    for (int k = threadIdx.x; k < 512; k += 128) s += x2[b * 512 + k] * W3[k];
    for (int o = 16; o > 0; o >>= 1) s += __shfl_down_sync(0xffffffffu, s, o);
    __shared__ float red[4];
    if ((threadIdx.x & 31) == 0) red[threadIdx.x >> 5] = s;
    __syncthreads();
    if (threadIdx.x == 0) {
        float t = red[0] + red[1] + red[2] + red[3] + b3[0];
        out[b] = 1.f / (1.f + expf(-t));
    }
}

// ---------------------------------------------------------------------------
extern "C" void kernel_launch(void* const* d_in, const int* in_sizes, int n_in,
                              void* d_out, int out_size) {
    const float* enc    = (const float*)d_in[0];
    const int*   seq    = (const int*)d_in[1];
    const float* emb    = (const float*)d_in[2];
    const float* l1f_Wi = (const float*)d_in[3];
    const float* l1f_Wh = (const float*)d_in[4];
    const float* l1f_b  = (const float*)d_in[5];
    const float* l1b_Wi = (const float*)d_in[6];
    const float* l1b_Wh = (const float*)d_in[7];
    const float* l1b_b  = (const float*)d_in[8];
    const float* l2f_Wi = (const float*)d_in[9];
    const float* l2f_Wh = (const float*)d_in[10];
    const float* l2f_b  = (const float*)d_in[11];
    const float* l2b_Wi = (const float*)d_in[12];
    const float* l2b_Wh = (const float*)d_in[13];
    const float* l2b_b  = (const float*)d_in[14];
    const float* W1     = (const float*)d_in[15];
    const float* b1     = (const float*)d_in[16];
    const float* W2     = (const float*)d_in[17];
    const float* b2     = (const float*)d_in[18];
    const float* W3     = (const float*)d_in[19];
    const float* b3     = (const float*)d_in[20];
    float* out = (float*)d_out;

    float *pooled, *xw, *seq1, *zbuf, *h, *c, *feats, *x1, *x2;
    cudaGetSymbolAddress((void**)&pooled, g_pooled);
    cudaGetSymbolAddress((void**)&xw, g_xw);
    cudaGetSymbolAddress((void**)&seq1, g_seq1);
    cudaGetSymbolAddress((void**)&zbuf, g_z);
    cudaGetSymbolAddress((void**)&h, g_h);
    cudaGetSymbolAddress((void**)&c, g_c);
    cudaGetSymbolAddress((void**)&feats, g_feats);
    cudaGetSymbolAddress((void**)&x1, g_x1);
    cudaGetSymbolAddress((void**)&x2, g_x2);

    cudaFuncSetAttribute(rec_persistent,
                         cudaFuncAttributeMaxDynamicSharedMemorySize, REC_SMEM);

    // 1. pooled mean
    pool_kernel<<<(Bsz * 2048 + 255) / 256, 256>>>(enc, pooled);

    // 2. layer-1 input projection (embedding gather fused)
    {
        dim3 grid(N2 / BN, ROWS / BM);
        tf32_gemm<<<grid, 256>>>(nullptr, emb, seq, EMB, l1f_Wi, l1b_Wi, G4,
                                 l1f_b, l1b_b, xw, N2, 0, 1);
    }

    // 3. layer-1 recurrence (persistent, 64 steps, Wh resident in smem)
    rec_persistent<<<NBLK, 256, REC_SMEM>>>(h, c, l1f_Wh, l1b_Wh, xw, seq, zbuf, seq1);

    // 4. layer-2 input projection (reuses xw buffer)
    {
        dim3 grid(N2 / BN, ROWS / BM);
        tf32_gemm<<<grid, 256>>>(seq1, nullptr, nullptr, 1024, l2f_Wi, l2b_Wi, G4,
                                 l2f_b, l2b_b, xw, N2, 0, 1);
    }

    // 5. layer-2 recurrence
    rec_persistent<<<NBLK, 256, REC_SMEM>>>(h, c, l2f_Wh, l2b_Wh, xw, seq, zbuf, nullptr);

    // 6. MLP head
    concat_kernel<<<(Bsz * 3072 + 255) / 256, 256>>>(pooled, h, feats);
    {
        dim3 grid(1024 / BN, Bsz / BM);
        tf32_gemm<<<grid, 256>>>(feats, nullptr, nullptr, 3072, W1, nullptr, 1024,
                                 b1, nullptr, x1, 1024, 1, 0);
    }
    {
        dim3 grid(512 / BN, Bsz / BM);
        tf32_gemm<<<grid, 256>>>(x1, nullptr, nullptr, 1024, W2, nullptr, 512,
                                 b2, nullptr, x2, 512, 1, 0);
    }
    final_kernel<<<Bsz, 128>>>(x2, W3, b3, out);
}

// round 4
// speedup vs baseline: 2.5344x; 1.2939x over previous
#include <cuda_runtime.h>
#include <cuda_bf16.h>
#include <math.h>

// Problem dims
#define Bsz 256
#define Tlen 64
#define EMB 256
#define UNITS 512
#define G4 2048          // 4*UNITS
#define N2 4096          // fwd+bwd gate width
#define ROWS (Bsz*Tlen)  // 16384

#define NBLK 128         // persistent grid size (single wave on 148 SMs)

// ---------------- scratch (device globals; no allocation allowed) ----------
__device__ float g_pooled[Bsz * 2048];
__device__ float g_xw[(size_t)ROWS * N2];      // 256 MiB, reused L1 then L2
__device__ float g_seq1[(size_t)ROWS * 1024];  // lstm1 output sequence
__device__ float g_h[2 * Bsz * UNITS];         // h ping buffer [dir][b][u]
__device__ float g_c[2 * Bsz * UNITS];         // h pong buffer (c lives in regs)
__device__ float g_feats[Bsz * 3072];
__device__ float g_x1[Bsz * 1024];
__device__ float g_x2[Bsz * 512];

// grid barrier state (monotone generation; self-resetting count)
__device__ unsigned g_bar_count;
__device__ volatile unsigned g_bar_gen;

__device__ __forceinline__ void grid_barrier() {
    __threadfence();
    __syncthreads();
    if (threadIdx.x == 0) {
        unsigned gen = g_bar_gen;
        __threadfence();
        if (atomicAdd(&g_bar_count, 1u) == NBLK - 1) {
            atomicExch(&g_bar_count, 0u);
            __threadfence();
            g_bar_gen = gen + 1;
        } else {
            while (g_bar_gen == gen) __nanosleep(32);
        }
    }
    __syncthreads();
}

// ================= TF32 helpers ============================================
// Raw fp32 bits fed as tf32: HW ignores low mantissa bits (truncation).
__device__ __forceinline__ void mma_tf32(float* d, const unsigned* a, const unsigned* b) {
    asm volatile(
        "mma.sync.aligned.m16n8k8.row.col.f32.tf32.tf32.f32 "
        "{%0,%1,%2,%3},{%4,%5,%6,%7},{%8,%9},{%0,%1,%2,%3};\n"
        : "+f"(d[0]), "+f"(d[1]), "+f"(d[2]), "+f"(d[3])
        : "r"(a[0]), "r"(a[1]), "r"(a[2]), "r"(a[3]), "r"(b[0]), "r"(b[1]));
}

__device__ __forceinline__ void cp16(void* smem_dst, const void* gsrc) {
    unsigned s = (unsigned)__cvta_generic_to_shared(smem_dst);
    asm volatile("cp.async.cg.shared.global [%0], [%1], 16;\n" :: "r"(s), "l"(gsrc));
}

// ================= big-tile cp.async TF32 GEMM =============================
// C[M, cstride] = A[M,K] @ W[K,*] (+bias, optional relu), 128x128 block tile,
// 8 warps of 64x32, double-buffered cp.async staging, raw-bit tf32.
#define BM2 128
#define BN2 128
#define AKS 20    // A smem [m][k] stride: 16 + 4 pad  (20 mod 32 -> conflict-free frags)
#define BNS 136   // B smem [k][n] stride: 128 + 8 pad (8 mod 32 -> conflict-free frags)
#define ABUF (BM2*AKS)   // 2560 floats
#define BBUF (16*BNS)    // 2176 floats

__global__ void __launch_bounds__(256)
tf32_gemm2(const float* __restrict__ A, const float* __restrict__ emb,
           const int* __restrict__ seq, int K,
           const float* __restrict__ Wf, const float* __restrict__ Wb, int wstride,
           const float* __restrict__ biasf, const float* __restrict__ biasb,
           float* __restrict__ C, int cstride, int relu, int split) {
    __shared__ float Asm[2][ABUF];
    __shared__ float Bsm[2][BBUF];

    int n0 = blockIdx.x * BN2;
    int m0 = blockIdx.y * BM2;
    const float* W = Wf;
    const float* bias = biasf;
    int nloc0 = n0;
    if (split && n0 >= G4) { W = Wb; bias = biasb; nloc0 = n0 - G4; }

    int tid = threadIdx.x;
    int wid = tid >> 5, lane = tid & 31;
    int g = lane >> 2, tg = lane & 3;
    int wm = (wid >> 2) * 64;   // 2 warps along M
    int wn = (wid & 3) * 32;    // 4 warps along N

    // A loader: row r = tid>>1, two 16B segs at k-offset (tid&1)*8 + {0,4}
    int ar = tid >> 1;
    int as0 = (tid & 1) * 8;
    const float* Arow = seq ? (emb + (size_t)seq[m0 + ar] * K)
                            : (A + (size_t)(m0 + ar) * K);
    // B loader: ops o = tid, tid+256 : k = o>>5, seg = o&31
    int bk0 = tid >> 5, bs0 = tid & 31;

    int niter = K >> 4;

    // stage(it, buf)
#define STAGE(IT, BUF) do {                                                     \
        int k0 = (IT) << 4;                                                     \
        cp16(&Asm[BUF][ar * AKS + as0],     Arow + k0 + as0);                   \
        cp16(&Asm[BUF][ar * AKS + as0 + 4], Arow + k0 + as0 + 4);               \
        cp16(&Bsm[BUF][bk0 * BNS + bs0 * 4],                                    \
             W + (size_t)(k0 + bk0) * wstride + nloc0 + bs0 * 4);               \
        cp16(&Bsm[BUF][(bk0 + 8) * BNS + bs0 * 4],                              \
             W + (size_t)(k0 + bk0 + 8) * wstride + nloc0 + bs0 * 4);           \
        asm volatile("cp.async.commit_group;\n");                               \
    } while (0)

    float acc[4][4][4] = {};

    STAGE(0, 0);
    for (int it = 0; it < niter; it++) {
        int buf = it & 1;
        if (it + 1 < niter) {
            STAGE(it + 1, buf ^ 1);
            asm volatile("cp.async.wait_group 1;\n");
        } else {
            asm volatile("cp.async.wait_group 0;\n");
        }
        __syncthreads();
        const float* As = Asm[buf];
        const float* Bs = Bsm[buf];
#pragma unroll
        for (int kb = 0; kb < 16; kb += 8) {
            unsigned a[4][4], b[4][2];
#pragma unroll
            for (int mi = 0; mi < 4; mi++) {
                int mr = wm + mi * 16 + g;
                a[mi][0] = __float_as_uint(As[mr * AKS + kb + tg]);
                a[mi][1] = __float_as_uint(As[(mr + 8) * AKS + kb + tg]);
                a[mi][2] = __float_as_uint(As[mr * AKS + kb + tg + 4]);
                a[mi][3] = __float_as_uint(As[(mr + 8) * AKS + kb + tg + 4]);
            }
#pragma unroll
            for (int ni = 0; ni < 4; ni++) {
                int nc = wn + ni * 8 + g;
                b[ni][0] = __float_as_uint(Bs[(kb + tg) * BNS + nc]);
                b[ni][1] = __float_as_uint(Bs[(kb + tg + 4) * BNS + nc]);
            }
#pragma unroll
            for (int mi = 0; mi < 4; mi++)
#pragma unroll
                for (int ni = 0; ni < 4; ni++)
                    mma_tf32(acc[mi][ni], a[mi], b[ni]);
        }
        __syncthreads();
    }
#undef STAGE

    // epilogue
#pragma unroll
    for (int mi = 0; mi < 4; mi++) {
#pragma unroll
        for (int rh = 0; rh < 2; rh++) {
            int row = m0 + wm + mi * 16 + g + rh * 8;
#pragma unroll
            for (int ni = 0; ni < 4; ni++) {
                int cl = wn + ni * 8 + 2 * tg;
                float v0 = acc[mi][ni][rh * 2 + 0] + bias[nloc0 + cl];
                float v1 = acc[mi][ni][rh * 2 + 1] + bias[nloc0 + cl + 1];
                if (relu) { v0 = fmaxf(v0, 0.f); v1 = fmaxf(v1, 0.f); }
                *(float2*)(C + (size_t)row * cstride + n0 + cl) = make_float2(v0, v1);
            }
        }
    }
}

// ================= persistent BiLSTM recurrence (fused gates) ==============
// 128 blocks = 2 m-tiles (128 batch) x 64 col-tiles. Block bn covers
// dir = bn>=32, u in [16*(bn&31), +16), all 4 gates (permuted columns:
// local col cl -> gate = cl>>4, uu = cl&15, natural col = gate*512+ub+uu).
// c and h live in registers (8 elems/thread); h double-buffered in gmem.
#define WH_STRIDE 72                  // 64 + 8 pad
#define AS_STRIDE 136                 // 128 + 8 pad (staging [k][m])
#define ZS_STRIDE 69                  // 64 + 5 pad (z tile [row][col])
#define UNION_SZ (128*ZS_STRIDE)      // 8832 >= 64*AS_STRIDE (8704)
#define REC_SMEM ((512*WH_STRIDE + UNION_SZ) * 4)

__global__ void __launch_bounds__(256, 1)
rec_persistent(float* __restrict__ hbuf0, float* __restrict__ hbuf1,
               const float* __restrict__ WhF, const float* __restrict__ WhB,
               const float* __restrict__ xw, const int* __restrict__ seq,
               float* __restrict__ out_seq) {
    extern __shared__ unsigned smem_dyn[];
    unsigned* Whs = smem_dyn;                       // [512][WH_STRIDE]
    unsigned* As  = smem_dyn + 512 * WH_STRIDE;     // [64][AS_STRIDE], reused as zs
    float*    zs  = (float*)As;                     // [128][ZS_STRIDE]

    int tid = threadIdx.x;
    int bn = blockIdx.x & 63;
    int bm = blockIdx.x >> 6;
    int dir = bn >> 5;
    int ub = (bn & 31) * 16;
    int m0 = bm * 128;
    const float* W = dir ? WhB : WhF;

    int wid = tid >> 5, lane = tid & 31;
    int g = lane >> 2, tg = lane & 3;
    int wm = (wid >> 1) * 32;   // 4 warps along M (128)
    int wn = (wid & 1) * 32;    // 2 warps along N (64)

    // ---- load permuted Wh tile into smem (raw fp32 bits) ----
    for (int i = tid; i < 512 * 64; i += 256) {
        int r = i >> 6, cl = i & 63;
        int nc = (cl >> 4) * 512 + ub + (cl & 15);
        Whs[r * WH_STRIDE + cl] = __float_as_uint(W[(size_t)r * G4 + nc]);
    }

    // ---- per-thread state slice: idx = tid + e*256; uu = idx&15, row = idx>>4
    float creg[8], hreg[8];
#pragma unroll
    for (int e = 0; e < 8; e++) { creg[e] = 0.f; hreg[e] = 0.f; }
    // zero own slice of h buffer 0 (read at t=0)
#pragma unroll
    for (int e = 0; e < 8; e++) {
        int idx = tid + e * 256;
        int row = idx >> 4, uu = idx & 15;
        hbuf0[dir * (Bsz * UNITS) + (m0 + row) * UNITS + ub + uu] = 0.f;
    }
    grid_barrier();

    // A staging coords ([k][m] layout, 16-k sub-chunks)
    int ar = tid >> 1;
    int ac = (tid & 1) * 2;

    for (int t = 0; t < Tlen; t++) {
        int te = dir ? (Tlen - 1 - t) : t;
        const float* hcur = (t & 1) ? hbuf1 : hbuf0;
        float* hnxt = (t & 1) ? hbuf0 : hbuf1;
        const float* Arow = hcur + dir * (Bsz * UNITS) + (size_t)(m0 + ar) * UNITS;

        // ========== GEMM: z_tile = h @ Wh_perm ==========
        float acc[2][4][4] = {};
        for (int k0 = 0; k0 < UNITS; k0 += 64) {
#pragma unroll
            for (int s = 0; s < 4; s++) {
#pragma unroll
                for (int j = 0; j < 2; j++) {
                    int c4 = ac + j;
                    float4 v = *(const float4*)(Arow + k0 + s * 16 + c4 * 4);
                    int kc = s * 16 + c4 * 4;
                    As[(kc + 0) * AS_STRIDE + ar] = __float_as_uint(v.x);
                    As[(kc + 1) * AS_STRIDE + ar] = __float_as_uint(v.y);
                    As[(kc + 2) * AS_STRIDE + ar] = __float_as_uint(v.z);
                    As[(kc + 3) * AS_STRIDE + ar] = __float_as_uint(v.w);
                }
            }
            __syncthreads();
#pragma unroll
            for (int kb = 0; kb < 64; kb += 8) {
                unsigned a[2][4], b[4][2];
#pragma unroll
                for (int mi = 0; mi < 2; mi++) {
                    int mr = wm + mi * 16;
                    a[mi][0] = As[(kb + tg) * AS_STRIDE + mr + g];
                    a[mi][1] = As[(kb + tg) * AS_STRIDE + mr + g + 8];
                    a[mi][2] = As[(kb + tg + 4) * AS_STRIDE + mr + g];
                    a[mi][3] = As[(kb + tg + 4) * AS_STRIDE + mr + g + 8];
                }
                int krow = k0 + kb;
#pragma unroll
                for (int ni = 0; ni < 4; ni++) {
                    int nc = wn + ni * 8;
                    b[ni][0] = Whs[(krow + tg) * WH_STRIDE + nc + g];
                    b[ni][1] = Whs[(krow + tg + 4) * WH_STRIDE + nc + g];
                }
#pragma unroll
                for (int mi = 0; mi < 2; mi++)
#pragma unroll
                    for (int ni = 0; ni < 4; ni++)
                        mma_tf32(acc[mi][ni], a[mi], b[ni]);
            }
            __syncthreads();
        }

        // ========== epilogue: z = acc + xw(te) -> smem z-tile ==========
#pragma unroll
        for (int mi = 0; mi < 2; mi++) {
#pragma unroll
            for (int rh = 0; rh < 2; rh++) {
                int lrow = wm + mi * 16 + g + rh * 8;   // local 0..127
                int b = m0 + lrow;
                const float* xrow = xw + ((size_t)b * Tlen + te) * N2 + dir * G4;
#pragma unroll
                for (int ni = 0; ni < 4; ni++) {
                    int cl = wn + ni * 8 + 2 * tg;
                    int gate = cl >> 4, uu = cl & 15;   // cl even -> same gate for cl,cl+1
                    float2 xv = *(const float2*)(xrow + gate * 512 + ub + uu);
                    zs[lrow * ZS_STRIDE + cl]     = acc[mi][ni][rh * 2 + 0] + xv.x;
                    zs[lrow * ZS_STRIDE + cl + 1] = acc[mi][ni][rh * 2 + 1] + xv.y;
                }
            }
        }
        __syncthreads();

        // ========== fused gates: c,h in registers ==========
#pragma unroll
        for (int e = 0; e < 8; e++) {
            int idx = tid + e * 256;
            int row = idx >> 4, uu = idx & 15;
            int b = m0 + row;
            float zi = zs[row * ZS_STRIDE + uu];
            float zf = zs[row * ZS_STRIDE + 16 + uu];
            float zg = zs[row * ZS_STRIDE + 32 + uu];
            float zo = zs[row * ZS_STRIDE + 48 + uu];
            float si = 1.f / (1.f + expf(-zi));
            float sf = 1.f / (1.f + expf(-zf));
            float so = 1.f / (1.f + expf(-zo));
            float cn = sf * creg[e] + si * tanhf(zg);
            float hn = so * tanhf(cn);
            if (seq[b * Tlen + te] != 0) { creg[e] = cn; hreg[e] = hn; }
            hnxt[dir * (Bsz * UNITS) + b * UNITS + ub + uu] = hreg[e];
            if (out_seq)
                out_seq[((size_t)b * Tlen + te) * 1024 + dir * 512 + ub + uu] = hreg[e];
        }
        __syncthreads();   // zs reuse as As next step (within block)
        grid_barrier();    // h(t+1) complete before anyone reads it
    }

    // publish final h into hbuf0 layout expectation handled by caller parity
}

// ---------------- pooled mean over 10x10 spatial ---------------------------
__global__ void pool_kernel(const float* __restrict__ enc, float* __restrict__ pooled) {
    int idx = blockIdx.x * blockDim.x + threadIdx.x;
    if (idx >= Bsz * 2048) return;
    int b = idx >> 11;
    int c = idx & 2047;
    const float* p = enc + (size_t)b * 100 * 2048 + c;
    float s = 0.f;
#pragma unroll 4
    for (int q = 0; q < 100; q++) s += p[q * 2048];
    pooled[idx] = s * 0.01f;
}

// ---------------- feats = concat(pooled, h_final_f, h_final_b) -------------
__global__ void concat_kernel(const float* __restrict__ pooled,
                              const float* __restrict__ h,
                              float* __restrict__ feats) {
    int idx = blockIdx.x * blockDim.x + threadIdx.x;
    if (idx >= Bsz * 3072) return;
    int b = idx / 3072;
    int k = idx - b * 3072;
    float v;
    if (k < 2048) v = pooled[b * 2048 + k];
    else {
        int kk = k - 2048;
        int dir = kk >> 9;
        int u = kk & 511;
        v = h[dir * 131072 + b * 512 + u];
    }
    feats[idx] = v;
}

// ---------------- final: sigmoid(x2 @ W3 + b3) -----------------------------
__global__ void final_kernel(const float* __restrict__ x2, const float* __restrict__ W3,
                             const float* __restrict__ b3, float* __restrict__ out) {
    int b = blockIdx.x;
    float s = 0.f;
    for (int k = threadIdx.x; k < 512; k += 128) s += x2[b * 512 + k] * W3[k];
    for (int o = 16; o > 0; o >>= 1) s += __shfl_down_sync(0xffffffffu, s, o);
    __shared__ float red[4];
    if ((threadIdx.x & 31) == 0) red[threadIdx.x >> 5] = s;
    __syncthreads();
    if (threadIdx.x == 0) {
        float t = red[0] + red[1] + red[2] + red[3] + b3[0];
        out[b] = 1.f / (1.f + expf(-t));
    }
}

// ---------------------------------------------------------------------------
extern "C" void kernel_launch(void* const* d_in, const int* in_sizes, int n_in,
                              void* d_out, int out_size) {
    const float* enc    = (const float*)d_in[0];
    const int*   seq    = (const int*)d_in[1];
    const float* emb    = (const float*)d_in[2];
    const float* l1f_Wi = (const float*)d_in[3];
    const float* l1f_Wh = (const float*)d_in[4];
    const float* l1f_b  = (const float*)d_in[5];
    const float* l1b_Wi = (const float*)d_in[6];
    const float* l1b_Wh = (const float*)d_in[7];
    const float* l1b_b  = (const float*)d_in[8];
    const float* l2f_Wi = (const float*)d_in[9];
    const float* l2f_Wh = (const float*)d_in[10];
    const float* l2f_b  = (const float*)d_in[11];
    const float* l2b_Wi = (const float*)d_in[12];
    const float* l2b_Wh = (const float*)d_in[13];
    const float* l2b_b  = (const float*)d_in[14];
    const float* W1     = (const float*)d_in[15];
    const float* b1     = (const float*)d_in[16];
    const float* W2     = (const float*)d_in[17];
    const float* b2     = (const float*)d_in[18];
    const float* W3     = (const float*)d_in[19];
    const float* b3     = (const float*)d_in[20];
    float* out = (float*)d_out;

    float *pooled, *xw, *seq1, *hb0, *hb1, *feats, *x1, *x2;
    cudaGetSymbolAddress((void**)&pooled, g_pooled);
    cudaGetSymbolAddress((void**)&xw, g_xw);
    cudaGetSymbolAddress((void**)&seq1, g_seq1);
    cudaGetSymbolAddress((void**)&hb0, g_h);
    cudaGetSymbolAddress((void**)&hb1, g_c);
    cudaGetSymbolAddress((void**)&feats, g_feats);
    cudaGetSymbolAddress((void**)&x1, g_x1);
    cudaGetSymbolAddress((void**)&x2, g_x2);

    cudaFuncSetAttribute(rec_persistent,
                         cudaFuncAttributeMaxDynamicSharedMemorySize, REC_SMEM);

    // final h (after 64 steps) lives in the buffer written at t=63: hnxt = hbuf0
    float* hfinal = hb0;

    // 1. pooled mean
    pool_kernel<<<(Bsz * 2048 + 255) / 256, 256>>>(enc, pooled);

    // 2. layer-1 input projection (embedding gather fused)
    {
        dim3 grid(N2 / BN2, ROWS / BM2);
        tf32_gemm2<<<grid, 256>>>(nullptr, emb, seq, EMB, l1f_Wi, l1b_Wi, G4,
                                  l1f_b, l1b_b, xw, N2, 0, 1);
    }

    // 3. layer-1 recurrence (persistent, fused gates, 1 barrier/step)
    rec_persistent<<<NBLK, 256, REC_SMEM>>>(hb0, hb1, l1f_Wh, l1b_Wh, xw, seq, seq1);

    // 4. layer-2 input projection (reuses xw buffer)
    {
        dim3 grid(N2 / BN2, ROWS / BM2);
        tf32_gemm2<<<grid, 256>>>(seq1, nullptr, nullptr, 1024, l2f_Wi, l2b_Wi, G4,
                                  l2f_b, l2b_b, xw, N2, 0, 1);
    }

    // 5. layer-2 recurrence
    rec_persistent<<<NBLK, 256, REC_SMEM>>>(hb0, hb1, l2f_Wh, l2b_Wh, xw, seq, nullptr);

    // 6. MLP head
    concat_kernel<<<(Bsz * 3072 + 255) / 256, 256>>>(pooled, hfinal, feats);
    {
        dim3 grid(1024 / BN2, Bsz / BM2);
        tf32_gemm2<<<grid, 256>>>(feats, nullptr, nullptr, 3072, W1, nullptr, 1024,
                                  b1, nullptr, x1, 1024, 1, 0);
    }
    {
        dim3 grid(512 / BN2, Bsz / BM2);
        tf32_gemm2<<<grid, 256>>>(x1, nullptr, nullptr, 1024, W2, nullptr, 512,
                                  b2, nullptr, x2, 512, 1, 0);
    }
    final_kernel<<<Bsz, 128>>>(x2, W3, b3, out);
}